// round 2
// baseline (speedup 1.0000x reference)
#include <cuda_runtime.h>

// SSIM over (32,3,512,512) fp32 pairs -> scalar mean.
// Crop [3:-3] => every used 7x7 window is fully interior: no padding logic.
// Pass 1 (vertical): column-per-thread sliding sums of {x,y,x2,y2,xy} read
//   DIRECTLY from global (coalesced across threads) -> 5 colsum smem arrays.
// Pass 2 (horizontal): register-sliding 7-sums over colsums -> SSIM -> reduce.

#define Hh 512
#define Ww 512
#define PLANES 96

#define TOR 16            // output rows per tile
#define TOC 128           // output cols per tile
#define IC (TOC + 6)      // 134 columns of colsums needed
#define PC (TOC + 7)      // 135: odd pitch for colsum arrays (bank spread)
#define NTHREADS 256

__device__ double g_acc;

__constant__ float c_invnp    = 1.0f / 49.0f;
__constant__ float c_convnorm = 49.0f / 48.0f;
__constant__ float c_c1       = 1e-4f;   // (0.01*1)^2
__constant__ float c_c2       = 9e-4f;   // (0.03*1)^2

__global__ void zero_acc_kernel() { g_acc = 0.0; }

__global__ void finalize_kernel(float* out) {
    // 96 planes * 506 * 506 valid pixels
    out[0] = (float)(g_acc / 24579456.0);
}

extern __shared__ float smem[];

__global__ __launch_bounds__(NTHREADS)
void ssim_kernel(const float* __restrict__ img1, const float* __restrict__ img2) {
    float* csx  = smem;                 // TOR*PC each
    float* csy  = csx  + TOR * PC;
    float* csxx = csy  + TOR * PC;
    float* csyy = csxx + TOR * PC;
    float* csxy = csyy + TOR * PC;

    const int tid   = threadIdx.x;
    const int plane = blockIdx.z;
    const int row0  = 3 + blockIdx.y * TOR;   // first output row (global)
    const int col0  = 3 + blockIdx.x * TOC;   // first output col (global)
    const int rcount = min(TOR, 509 - row0);  // valid out rows in this tile
    const int ccount = min(TOC, 509 - col0);  // valid out cols in this tile

    const float* __restrict__ p1 = img1 + (size_t)plane * (Hh * Ww);
    const float* __restrict__ p2 = img2 + (size_t)plane * (Hh * Ww);

    // ---- Pass 1: vertical sliding column sums straight from global ----
    // Task t: column c of the tile, out-rows [ro, ro+8). 2*IC = 268 tasks.
    for (int t = tid; t < 2 * IC; t += NTHREADS) {
        int c = t, ro = 0;
        if (t >= IC) { c = t - IC; ro = 8; }
        int gc = col0 - 3 + c; if (gc > 511) gc = 511;
        const int gr0 = row0 - 3 + ro;        // first input row for this task

        float ax = 0.f, ay = 0.f, axx = 0.f, ayy = 0.f, axy = 0.f;
        #pragma unroll
        for (int k = 0; k < 7; k++) {
            int gr = gr0 + k; if (gr > 511) gr = 511;
            float x = __ldg(p1 + gr * Ww + gc);
            float y = __ldg(p2 + gr * Ww + gc);
            ax += x; ay += y;
            axx = fmaf(x, x, axx); ayy = fmaf(y, y, ayy); axy = fmaf(x, y, axy);
        }
        int rr = ro * PC + c;
        csx[rr] = ax; csy[rr] = ay; csxx[rr] = axx; csyy[rr] = ayy; csxy[rr] = axy;

        #pragma unroll
        for (int i = 1; i < 8; i++) {
            int grn = gr0 + i + 6; if (grn > 511) grn = 511;
            int gro = gr0 + i - 1; if (gro > 511) gro = 511;
            float xn = __ldg(p1 + grn * Ww + gc);
            float yn = __ldg(p2 + grn * Ww + gc);
            float xo = __ldg(p1 + gro * Ww + gc);
            float yo = __ldg(p2 + gro * Ww + gc);
            ax += xn - xo;
            ay += yn - yo;
            axx += fmaf(xn, xn, -xo * xo);
            ayy += fmaf(yn, yn, -yo * yo);
            axy += fmaf(xn, yn, -xo * yo);
            rr = (ro + i) * PC + c;
            csx[rr] = ax; csy[rr] = ay; csxx[rr] = axx; csyy[rr] = ayy; csxy[rr] = axy;
        }
    }
    __syncthreads();

    // ---- Pass 2: horizontal register-sliding sums + SSIM ----
    float acc = 0.0f;
    {
        const int row = tid & 15;        // 0..15
        const int seg = tid >> 4;        // 0..15
        const int jb  = seg * 8;         // first local out col of this segment
        if (row < rcount) {
            float wx[8], wy[8], wxx[8], wyy[8], wxy[8];
            const int base = row * PC + jb;

            auto hsum = [&](const float* __restrict__ cs, float* w) {
                float v[14];
                #pragma unroll
                for (int k = 0; k < 14; k++) v[k] = cs[base + k];
                float s = v[0] + v[1] + v[2] + v[3] + v[4] + v[5] + v[6];
                w[0] = s;
                #pragma unroll
                for (int k = 0; k < 7; k++) { s += v[7 + k] - v[k]; w[k + 1] = s; }
            };
            hsum(csx,  wx);
            hsum(csy,  wy);
            hsum(csxx, wxx);
            hsum(csyy, wyy);
            hsum(csxy, wxy);

            int nvalid = ccount - jb;    // >= 2 for all scheduled tiles
            if (nvalid > 8) nvalid = 8;
            #pragma unroll
            for (int j = 0; j < 8; j++) {
                if (j < nvalid) {
                    float ux  = wx[j]  * c_invnp;
                    float uy  = wy[j]  * c_invnp;
                    float uxx = wxx[j] * c_invnp;
                    float uyy = wyy[j] * c_invnp;
                    float uxy = wxy[j] * c_invnp;
                    float vx  = c_convnorm * (uxx - ux * ux);
                    float vy  = c_convnorm * (uyy - uy * uy);
                    float vxy = c_convnorm * (uxy - ux * uy);
                    float A1 = 2.0f * ux * uy + c_c1;
                    float A2 = 2.0f * vxy + c_c2;
                    float B1 = ux * ux + uy * uy + c_c1;
                    float B2 = vx + vy + c_c2;
                    acc += (A1 * A2) * __fdividef(1.0f, B1 * B2);
                }
            }
        }
    }

    // ---- block reduction ----
    #pragma unroll
    for (int off = 16; off > 0; off >>= 1)
        acc += __shfl_down_sync(0xffffffffu, acc, off);

    __shared__ float wsum[NTHREADS / 32];
    const int lane = tid & 31;
    const int wid  = tid >> 5;
    if (lane == 0) wsum[wid] = acc;
    __syncthreads();
    if (tid == 0) {
        float s = 0.f;
        #pragma unroll
        for (int i = 0; i < NTHREADS / 32; i++) s += wsum[i];
        atomicAdd(&g_acc, (double)s);
    }
}

extern "C" void kernel_launch(void* const* d_in, const int* in_sizes, int n_in,
                              void* d_out, int out_size) {
    const float* img1 = (const float*)d_in[0];
    const float* img2 = (const float*)d_in[1];
    float* out = (float*)d_out;

    const size_t smem_bytes = (size_t)(5 * TOR * PC) * sizeof(float); // 43,200 B
    cudaFuncSetAttribute(ssim_kernel, cudaFuncAttributeMaxDynamicSharedMemorySize,
                         (int)smem_bytes);

    zero_acc_kernel<<<1, 1>>>();
    dim3 grid((506 + TOC - 1) / TOC, (506 + TOR - 1) / TOR, PLANES);  // (4, 32, 96)
    ssim_kernel<<<grid, NTHREADS, smem_bytes>>>(img1, img2);
    finalize_kernel<<<1, 1>>>(out);
}

// round 11
// speedup vs baseline: 1.0689x; 1.0689x over previous
#include <cuda_runtime.h>

// SSIM over (32,3,512,512) fp32 pairs -> scalar mean. Single fused kernel.
// Crop [3:-3] => every used 7x7 window is fully interior: no padding logic.
// Pass 1 (vertical): one column-task per thread (268 tasks, 288 threads),
//   sliding sums of {x,y,x2,y2,xy} read directly from global (coalesced),
//   7-deep register ring buffer -> 5 colsum smem arrays.
// Pass 2 (horizontal): fused register-sliding 7-sum + immediate SSIM emit
//   (no w[8] arrays -> ~55 live regs, no spills at launch_bounds(288,3)).
// Epilogue: block partial -> double atomicAdd -> last block writes out[0]
//   and resets accumulators (graph-replay deterministic; statics init to 0).

#define Hh 512
#define Ww 512
#define PLANES 96

#define TOR 16            // output rows per tile
#define TOC 128           // output cols per tile
#define IC (TOC + 6)      // 134 columns of colsums needed
#define PC (TOC + 7)      // 135: odd pitch (pass-2 proven conflict-free)
#define NTHREADS 288      // >= 2*IC = 268 pass-1 tasks -> one task per thread
#define NBLOCKS (4 * 32 * 96)   // grid size = 12288

__device__ double g_acc;          // static-zero initialized
__device__ unsigned int g_cnt;    // static-zero initialized

__constant__ float c_invnp    = 1.0f / 49.0f;
__constant__ float c_convnorm = 49.0f / 48.0f;
__constant__ float c_c1       = 1e-4f;   // (0.01*1)^2
__constant__ float c_c2       = 9e-4f;   // (0.03*1)^2

extern __shared__ float smem[];

__device__ __forceinline__ float ssim_px(float sx, float sy, float sxx,
                                         float syy, float sxy) {
    float ux  = sx  * c_invnp;
    float uy  = sy  * c_invnp;
    float uxx = sxx * c_invnp;
    float uyy = syy * c_invnp;
    float uxy = sxy * c_invnp;
    float vx  = c_convnorm * (uxx - ux * ux);
    float vy  = c_convnorm * (uyy - uy * uy);
    float vxy = c_convnorm * (uxy - ux * uy);
    float A1 = 2.0f * ux * uy + c_c1;
    float A2 = 2.0f * vxy + c_c2;
    float B1 = ux * ux + uy * uy + c_c1;
    float B2 = vx + vy + c_c2;
    return (A1 * A2) * __fdividef(1.0f, B1 * B2);
}

__global__ __launch_bounds__(NTHREADS, 3)
void ssim_kernel(const float* __restrict__ img1, const float* __restrict__ img2,
                 float* __restrict__ out) {
    float* csx  = smem;                 // TOR*PC each
    float* csy  = csx  + TOR * PC;
    float* csxx = csy  + TOR * PC;
    float* csyy = csxx + TOR * PC;
    float* csxy = csyy + TOR * PC;

    const int tid   = threadIdx.x;
    const int plane = blockIdx.z;
    const int row0  = 3 + blockIdx.y * TOR;   // first output row (global)
    const int col0  = 3 + blockIdx.x * TOC;   // first output col (global)
    const int rcount = min(TOR, 509 - row0);
    const int ccount = min(TOC, 509 - col0);

    const float* __restrict__ p1 = img1 + (size_t)plane * (Hh * Ww);
    const float* __restrict__ p2 = img2 + (size_t)plane * (Hh * Ww);

    // ---- Pass 1: vertical sliding column sums from global, ring buffer ----
    // Task t: column c of the tile, out-rows [ro, ro+8). One task per thread.
    if (tid < 2 * IC) {
        int c = tid, ro = 0;
        if (tid >= IC) { c = tid - IC; ro = 8; }
        const int gc  = min(col0 - 3 + c, 511);
        const int gr0 = row0 - 3 + ro;

        float rx[7], ry[7];
        float ax = 0.f, ay = 0.f, axx = 0.f, ayy = 0.f, axy = 0.f;
        #pragma unroll
        for (int k = 0; k < 7; k++) {
            const int gr = min(gr0 + k, 511);
            float x = __ldg(p1 + gr * Ww + gc);
            float y = __ldg(p2 + gr * Ww + gc);
            rx[k] = x; ry[k] = y;
            ax += x; ay += y;
            axx = fmaf(x, x, axx); ayy = fmaf(y, y, ayy); axy = fmaf(x, y, axy);
        }
        int rr = ro * PC + c;
        csx[rr] = ax; csy[rr] = ay; csxx[rr] = axx; csyy[rr] = ayy; csxy[rr] = axy;

        #pragma unroll
        for (int i = 1; i < 8; i++) {
            const int grn = min(gr0 + i + 6, 511);
            float xn = __ldg(p1 + grn * Ww + gc);
            float yn = __ldg(p2 + grn * Ww + gc);
            const int old = (i - 1) % 7;     // compile-time after unroll
            float xo = rx[old], yo = ry[old];
            ax += xn - xo;
            ay += yn - yo;
            axx += fmaf(xn, xn, -xo * xo);
            ayy += fmaf(yn, yn, -yo * yo);
            axy += fmaf(xn, yn, -xo * yo);
            rx[old] = xn; ry[old] = yn;
            rr = (ro + i) * PC + c;
            csx[rr] = ax; csy[rr] = ay; csxx[rr] = axx; csyy[rr] = ayy; csxy[rr] = axy;
        }
    }
    __syncthreads();

    // ---- Pass 2: fused horizontal sliding sums + SSIM ----
    float acc = 0.0f;
    {
        const int row = tid & 15;        // 0..15
        const int seg = tid >> 4;        // 0..17 (segs >= 16 idle)
        const int jb  = seg * 8;
        if (seg < 16 && row < rcount) {
            const int base = row * PC + jb;
            int nvalid = ccount - jb;    // >= 2 for all scheduled tiles
            if (nvalid > 8) nvalid = 8;

            // histories (35 regs) + running sums (5 regs)
            float vx7[7], vy7[7], vxx7[7], vyy7[7], vxy7[7];
            float sx = 0.f, sy = 0.f, sxx = 0.f, syy = 0.f, sxy = 0.f;
            #pragma unroll
            for (int k = 0; k < 7; k++) {
                float a = csx [base + k]; vx7 [k] = a; sx  += a;
                float b = csy [base + k]; vy7 [k] = b; sy  += b;
                float d = csxx[base + k]; vxx7[k] = d; sxx += d;
                float e = csyy[base + k]; vyy7[k] = e; syy += e;
                float f = csxy[base + k]; vxy7[k] = f; sxy += f;
            }
            acc += ssim_px(sx, sy, sxx, syy, sxy);   // j = 0 (always valid)

            const int lead = base + 7;   // one base reg, constant offsets
            #pragma unroll
            for (int j = 1; j < 8; j++) {
                const int k = j - 1;
                sx  += csx [lead + k] - vx7 [k];
                sy  += csy [lead + k] - vy7 [k];
                sxx += csxx[lead + k] - vxx7[k];
                syy += csyy[lead + k] - vyy7[k];
                sxy += csxy[lead + k] - vxy7[k];
                if (j < nvalid)
                    acc += ssim_px(sx, sy, sxx, syy, sxy);
            }
        }
    }

    // ---- block reduction (288 threads = 9 warps) ----
    #pragma unroll
    for (int off = 16; off > 0; off >>= 1)
        acc += __shfl_down_sync(0xffffffffu, acc, off);

    __shared__ float wsum[NTHREADS / 32];
    const int lane = tid & 31;
    const int wid  = tid >> 5;
    if (lane == 0) wsum[wid] = acc;
    __syncthreads();

    if (tid == 0) {
        float s = 0.f;
        #pragma unroll
        for (int i = 0; i < NTHREADS / 32; i++) s += wsum[i];
        atomicAdd(&g_acc, (double)s);
        __threadfence();
        unsigned int old = atomicAdd(&g_cnt, 1u);
        if (old == NBLOCKS - 1) {
            // last block: finalize and reset for next graph replay
            double v = *((volatile double*)&g_acc);
            out[0] = (float)(v / 24579456.0);   // 96 * 506 * 506
            g_acc = 0.0;
            __threadfence();
            g_cnt = 0u;
        }
    }
}

extern "C" void kernel_launch(void* const* d_in, const int* in_sizes, int n_in,
                              void* d_out, int out_size) {
    const float* img1 = (const float*)d_in[0];
    const float* img2 = (const float*)d_in[1];
    float* out = (float*)d_out;

    const size_t smem_bytes = (size_t)(5 * TOR * PC) * sizeof(float); // 43,200 B
    cudaFuncSetAttribute(ssim_kernel, cudaFuncAttributeMaxDynamicSharedMemorySize,
                         (int)smem_bytes);

    dim3 grid((506 + TOC - 1) / TOC, (506 + TOR - 1) / TOR, PLANES);  // (4, 32, 96)
    ssim_kernel<<<grid, NTHREADS, smem_bytes>>>(img1, img2, out);
}

// round 13
// speedup vs baseline: 1.5049x; 1.4079x over previous
#include <cuda_runtime.h>

// SSIM over (32,3,512,512) fp32 pairs -> scalar mean. Single fused kernel.
// Zero-smem, warp-autonomous design (R11 profile: L1tex 63.4% was the wall).
// Each warp-task owns a (plane, 120-col span, 46-row strip). Thread = 4 cols
// (float4). Vertical 7-row sliding sums of {x,y,x2,y2,xy} kept in registers;
// outgoing row RELOADED from global (L1-resident) instead of a register ring.
// Horizontal 7-window sums via 6 lane-shuffles per quantity (halo from
// neighbor lanes) + sliding adds. No STS/LDS/syncthreads in the hot loop.
// Coverage: out cols 3..508 = 5 spans x local cols [3,122] (exact, disjoint);
// out rows 3..508 = 11 strips x 46 rows (exact).

#define PLANES   96
#define NSPAN    5
#define NRS      11
#define RPT      46
#define TASKS    (PLANES * NSPAN * NRS)   // 5280 warp-tasks
#define NTHREADS 128
#define NBLOCKS  (TASKS / 4)              // 1320 blocks (4 warps each)

__device__ double g_acc;          // static-zero initialized
__device__ unsigned int g_cnt;    // static-zero initialized

// SSIM from raw 7x7 window sums w* (scales folded into constants):
// ux = wx/49 etc., cn = 49/48.
// A1 = 2*ux*uy + C1            = (2/2401)*wx*wy + C1
// A2 = 2*cn*(uxy - ux*uy) + C2 = wxy/24 - wx*wy/1176 + C2
// B1 = ux^2 + uy^2 + C1        = (wx^2+wy^2)/2401 + C1
// B2 = cn*(uxx+uyy - ux^2-uy^2) + C2 = (wxx+wyy)/48 - (wx^2+wy^2)/2352 + C2
__device__ __forceinline__ float ssim_px(float wx, float wy, float wxx,
                                         float wyy, float wxy) {
    const float C1 = 1e-4f, C2 = 9e-4f;
    float P  = wx * wy;
    float Q  = fmaf(wx, wx, wy * wy);
    float A1 = fmaf(P, 2.0f / 2401.0f, C1);
    float A2 = fmaf(wxy, 1.0f / 24.0f, fmaf(P, -1.0f / 1176.0f, C2));
    float B1 = fmaf(Q, 1.0f / 2401.0f, C1);
    float B2 = fmaf(wxx + wyy, 1.0f / 48.0f, fmaf(Q, -1.0f / 2352.0f, C2));
    return (A1 * A2) * __fdividef(1.0f, B1 * B2);
}

__global__ __launch_bounds__(NTHREADS)
void ssim_kernel(const float* __restrict__ img1, const float* __restrict__ img2,
                 float* __restrict__ out) {
    const int lane = threadIdx.x & 31;
    const int task = (blockIdx.x << 2) + (threadIdx.x >> 5);

    const int plane  = task / (NSPAN * NRS);
    const int rem    = task - plane * (NSPAN * NRS);
    const int span   = rem / NRS;
    const int rstrip = rem - span * NRS;

    const int R0 = 3 + rstrip * RPT;          // first output row
    const int cb = span * 120 + (lane << 2);  // thread's first column
    const bool ldok = (cb + 3) <= 511;        // whole float4 in-bounds

    // Output validity per j: local col in [3,122] and global col <= 508.
    bool val[4];
    #pragma unroll
    for (int j = 0; j < 4; j++) {
        int lc = (lane << 2) + j;
        val[j] = (lc >= 3) && (lc <= 122) && ((cb + j) <= 508);
    }

    const float* b1 = img1 + (size_t)plane * 262144;
    const float* b2 = img2 + (size_t)plane * 262144;
    const float4* p1n = reinterpret_cast<const float4*>(b1 + (R0 - 3) * 512 + cb);
    const float4* p2n = reinterpret_cast<const float4*>(b2 + (R0 - 3) * 512 + cb);
    const float4* p1o = p1n;                  // trails 7 rows behind
    const float4* p2o = p2n;

    float sx[4]  = {0.f, 0.f, 0.f, 0.f};
    float sy[4]  = {0.f, 0.f, 0.f, 0.f};
    float sxx[4] = {0.f, 0.f, 0.f, 0.f};
    float syy[4] = {0.f, 0.f, 0.f, 0.f};
    float sxy[4] = {0.f, 0.f, 0.f, 0.f};

    const float4 z4 = make_float4(0.f, 0.f, 0.f, 0.f);

    // Warmup: accumulate rows R0-3 .. R0+3 (7 rows).
    #pragma unroll 1
    for (int k = 0; k < 7; k++) {
        float4 X = ldok ? __ldg(p1n) : z4;
        float4 Y = ldok ? __ldg(p2n) : z4;
        p1n += 128; p2n += 128;
        float xs[4] = {X.x, X.y, X.z, X.w};
        float ys[4] = {Y.x, Y.y, Y.z, Y.w};
        #pragma unroll
        for (int j = 0; j < 4; j++) {
            sx[j] += xs[j];
            sy[j] += ys[j];
            sxx[j] = fmaf(xs[j], xs[j], sxx[j]);
            syy[j] = fmaf(ys[j], ys[j], syy[j]);
            sxy[j] = fmaf(xs[j], ys[j], sxy[j]);
        }
    }

    float acc = 0.f;

    // Horizontal 7-window from column sums cs[0..3] + neighbor halos.
    // Lane-edge shuffle garbage cancels exactly in the sliding chain
    // (added in w0, subtracted before any lane-valid output uses it).
    auto hwin = [&](const float* cs, float* w) {
        float L1 = __shfl_up_sync(0xffffffffu, cs[1], 1);
        float L2 = __shfl_up_sync(0xffffffffu, cs[2], 1);
        float L3 = __shfl_up_sync(0xffffffffu, cs[3], 1);
        float Ra = __shfl_down_sync(0xffffffffu, cs[0], 1);
        float Rb = __shfl_down_sync(0xffffffffu, cs[1], 1);
        float Rc = __shfl_down_sync(0xffffffffu, cs[2], 1);
        w[0] = ((L1 + L2) + (L3 + cs[0])) + ((cs[1] + cs[2]) + cs[3]);
        w[1] = (w[0] - L1) + Ra;
        w[2] = (w[1] - L2) + Rb;
        w[3] = (w[2] - L3) + Rc;
    };

    auto emit = [&]() {
        float wx[4], wy[4], wxx[4], wyy[4], wxy[4];
        hwin(sx,  wx);
        hwin(sy,  wy);
        hwin(sxx, wxx);
        hwin(syy, wyy);
        hwin(sxy, wxy);
        #pragma unroll
        for (int j = 0; j < 4; j++)
            if (val[j]) acc += ssim_px(wx[j], wy[j], wxx[j], wyy[j], wxy[j]);
    };

    emit();   // output row R0

    #pragma unroll 1
    for (int it = 1; it < RPT; ++it) {
        float4 XN = ldok ? __ldg(p1n) : z4;   // row R0+3+it (new)
        float4 YN = ldok ? __ldg(p2n) : z4;
        float4 XO = ldok ? __ldg(p1o) : z4;   // row R0-4+it (outgoing, L1-hot)
        float4 YO = ldok ? __ldg(p2o) : z4;
        p1n += 128; p2n += 128; p1o += 128; p2o += 128;
        float xn[4] = {XN.x, XN.y, XN.z, XN.w};
        float yn[4] = {YN.x, YN.y, YN.z, YN.w};
        float xo[4] = {XO.x, XO.y, XO.z, XO.w};
        float yo[4] = {YO.x, YO.y, YO.z, YO.w};
        #pragma unroll
        for (int j = 0; j < 4; j++) {
            sx[j] += xn[j] - xo[j];
            sy[j] += yn[j] - yo[j];
            sxx[j] = fmaf(xn[j], xn[j], sxx[j] - xo[j] * xo[j]);
            syy[j] = fmaf(yn[j], yn[j], syy[j] - yo[j] * yo[j]);
            sxy[j] = fmaf(xn[j], yn[j], sxy[j] - xo[j] * yo[j]);
        }
        emit();   // output row R0+it
    }

    // ---- reduction: warp -> block -> global double ----
    #pragma unroll
    for (int off = 16; off > 0; off >>= 1)
        acc += __shfl_down_sync(0xffffffffu, acc, off);

    __shared__ float wsum[NTHREADS / 32];
    const int wid = threadIdx.x >> 5;
    if (lane == 0) wsum[wid] = acc;
    __syncthreads();

    if (threadIdx.x == 0) {
        float s = wsum[0] + wsum[1] + wsum[2] + wsum[3];
        atomicAdd(&g_acc, (double)s);
        __threadfence();
        unsigned int old = atomicAdd(&g_cnt, 1u);
        if (old == NBLOCKS - 1) {
            double v = *((volatile double*)&g_acc);
            out[0] = (float)(v / 24579456.0);   // 96 * 506 * 506
            g_acc = 0.0;
            __threadfence();
            g_cnt = 0u;
        }
    }
}

extern "C" void kernel_launch(void* const* d_in, const int* in_sizes, int n_in,
                              void* d_out, int out_size) {
    const float* img1 = (const float*)d_in[0];
    const float* img2 = (const float*)d_in[1];
    float* out = (float*)d_out;

    ssim_kernel<<<NBLOCKS, NTHREADS>>>(img1, img2, out);
}